// round 12
// baseline (speedup 1.0000x reference)
#include <cuda_runtime.h>
#include <stdint.h>
#include <math.h>

#define SEQN 320
#define HN   400
#define GN   1600
#define NP1  321
#define CLU  16          // CTAs per direction (cluster size, non-portable)
#define DPC  25          // h-dims per CTA
#define TPB  416         // 13 warps; 26 groups of 16 lanes (group 25 is dummy)
#define HPAD 448         // padded h buffer: 16 chunks * 28 floats

// ---------------- scratch (static device globals; no allocation) ----------------
__device__ float g_x[SEQN * HN];
__device__ float g_G0[2][SEQN * GN];        // layer0 [dir] (unsplit K)
__device__ float g_G1[2][2][SEQN * GN];     // layer1 [dir][khalf]
__device__ float g_y0[SEQN * 800];
__device__ float g_hv[SEQN * 800];
__device__ float g_A[2][SEQN * GN];         // [khalf]
__device__ float g_B[2][SEQN * GN];         // [khalf]

// ---------------- embedding gather ----------------
__global__ void k_embed(const int* __restrict__ words, const int* __restrict__ tags,
                        const float* __restrict__ wemb, const float* __restrict__ temb) {
    int idx = blockIdx.x * blockDim.x + threadIdx.x;
    if (idx >= SEQN * HN) return;
    int t = idx / HN, j = idx % HN;
    g_x[idx] = (j < 300) ? wemb[(size_t)words[t] * 300 + j]
                         : temb[(size_t)tags[t] * 100 + (j - 300)];
}

// ---------------- fused NT GEMM: problems via z&1, K-halves via z>>1 --------
// C[320][1600] = X[:, xofs:xofs+Khalf] * W[:, wofs:wofs+Khalf].T (+ biases on half 0)
__global__ void __launch_bounds__(256)
k_gemm2(const float* __restrict__ X, int ldx,
        const float* __restrict__ W0, const float* __restrict__ W1, int ldw,
        int wofs0, int wofs1,
        const float* __restrict__ b1a, const float* __restrict__ b1b,
        const float* __restrict__ b2a, const float* __restrict__ b2b,
        float* __restrict__ C0a, float* __restrict__ C0b,
        float* __restrict__ C1a, float* __restrict__ C1b, int Khalf) {
    const int prob = blockIdx.z & 1;
    const int half = blockIdx.z >> 1;
    const float* W  = prob ? W1 : W0;
    const int  wofs = (prob ? wofs1 : wofs0) + half * Khalf;
    const int  xofs = half * Khalf;
    const float* b1 = half ? nullptr : (prob ? b1b : b1a);
    const float* b2 = half ? nullptr : (prob ? b2b : b2a);
    float*       C  = prob ? (half ? C1b : C1a) : (half ? C0b : C0a);

    __shared__ __align__(16) float Xs[2][16][64];
    __shared__ __align__(16) float Ws[2][16][64];
    int tid = threadIdx.x;
    int tx = tid & 15, ty = tid >> 4;
    int row0 = blockIdx.x * 64, col0 = blockIdx.y * 64;
    int lk = tid & 15, lm0 = tid >> 4;

    float acc[4][4] = {};
    const int nch = Khalf / 16;

#pragma unroll
    for (int p = 0; p < 4; p++) {
        int m = lm0 + p * 16;
        Xs[0][lk][m] = X[(size_t)(row0 + m) * ldx + xofs + lk];
        Ws[0][lk][m] = W[(size_t)(col0 + m) * ldw + wofs + lk];
    }
    __syncthreads();

    int cur = 0;
    for (int i = 0; i < nch; i++) {
        if (i + 1 < nch) {
            int k0 = (i + 1) * 16;
#pragma unroll
            for (int p = 0; p < 4; p++) {
                int m = lm0 + p * 16;
                Xs[cur ^ 1][lk][m] = X[(size_t)(row0 + m) * ldx + xofs + k0 + lk];
                Ws[cur ^ 1][lk][m] = W[(size_t)(col0 + m) * ldw + wofs + k0 + lk];
            }
        }
#pragma unroll
        for (int kk = 0; kk < 16; kk++) {
            float4 a = *reinterpret_cast<const float4*>(&Xs[cur][kk][ty * 4]);
            float4 b = *reinterpret_cast<const float4*>(&Ws[cur][kk][tx * 4]);
            float av[4] = {a.x, a.y, a.z, a.w};
            float bv[4] = {b.x, b.y, b.z, b.w};
#pragma unroll
            for (int ii = 0; ii < 4; ii++)
#pragma unroll
                for (int j = 0; j < 4; j++)
                    acc[ii][j] = fmaf(av[ii], bv[j], acc[ii][j]);
        }
        __syncthreads();
        cur ^= 1;
    }
#pragma unroll
    for (int i = 0; i < 4; i++) {
#pragma unroll
        for (int j = 0; j < 4; j++) {
            int n = col0 + tx * 4 + j;
            float bias = 0.f;
            if (b1) bias += b1[n];
            if (b2) bias += b2[n];
            C[(size_t)(row0 + ty * 4 + i) * GN + n] = acc[i][j] + bias;
        }
    }
}

// ---------------- cluster BiLSTM ----------------
__device__ __forceinline__ float tanh_apx(float x) {
    float y;
    asm("tanh.approx.f32 %0, %1;" : "=f"(y) : "f"(x));
    return y;
}
__device__ __forceinline__ float sig_apx(float x) {
    return fmaf(0.5f, tanh_apx(0.5f * x), 0.5f);
}
__device__ __forceinline__ uint32_t s2u(const void* p) {
    uint32_t a;
    asm("{ .reg .u64 t; cvta.to.shared.u64 t, %1; cvt.u32.u64 %0, t; }" : "=r"(a) : "l"(p));
    return a;
}
__device__ __forceinline__ unsigned long long pack2(float lo, float hi) {
    unsigned long long p;
    asm("mov.b64 %0, {%1, %2};" : "=l"(p) : "f"(lo), "f"(hi));
    return p;
}
__device__ __forceinline__ void fma2(unsigned long long& acc, unsigned long long a,
                                     unsigned long long b) {
    asm("fma.rn.f32x2 %0, %1, %2, %0;" : "+l"(acc) : "l"(a), "l"(b));
}
__device__ __forceinline__ float hsum2(unsigned long long p) {
    float lo, hi;
    asm("mov.b64 {%0, %1}, %2;" : "=f"(lo), "=f"(hi) : "l"(p));
    return lo + hi;
}

// grid (32), cluster (16): blocks 0-15 = forward, 16-31 = backward.
// Per step: compute -> pair-packed st.shared::cluster.v2 broadcast (208 remote
// stores/CTA) -> bar -> 16 remote mbarrier.arrive.release.cluster -> local
// try_wait.parity (HW sleep). Y is staged in SMEM, dumped once at the end —
// no GMEM store in the recurrent loop's release window.
__global__ void __launch_bounds__(TPB, 1)
k_lstm(const float* __restrict__ whh_f, const float* __restrict__ whh_b,
       const float* __restrict__ h0, const float* __restrict__ c0, int layer) {
    const int dir = blockIdx.x >> 4;
    const int cta = blockIdx.x & 15;
    const float* Ga = (layer == 0) ? g_G0[dir] : g_G1[dir][0];
    const float* Gb = (layer == 0) ? (const float*)0 : g_G1[dir][1];
    float*       Y  = (layer == 0) ? g_y0 : g_hv;
    const float* whh = dir ? whh_b : whh_f;
    const float* h0row = h0 + (size_t)(2 * layer + dir) * HN;
    const float* c0row = c0 + (size_t)(2 * layer + dir) * HN;

    const int tid = threadIdx.x;
    const int grp = tid >> 4;        // 0..25 (25 = dummy)
    const int lc  = tid & 15;
    const bool active = grp < DPC;
    const int dim = cta * DPC + grp;
    const int wbase = tid & 16;      // group base lane within warp

    __shared__ __align__(16) float sh_h[2][HPAD];
    __shared__ float sh_y[SEQN][DPC];                 // 32 KB staging for Y
    __shared__ __align__(8) unsigned long long sh_mbar;

    // ---- register-resident recurrent weights, packed f32x2 ----
    unsigned long long wI[12], wF[12], wG[12], wO[12];
    float wIt = 0.f, wFt = 0.f, wGt = 0.f, wOt = 0.f;
    if (active) {
        const float* pI = whh + (size_t)(dim)        * HN + lc * 25;
        const float* pF = whh + (size_t)(400 + dim)  * HN + lc * 25;
        const float* pG = whh + (size_t)(800 + dim)  * HN + lc * 25;
        const float* pO = whh + (size_t)(1200 + dim) * HN + lc * 25;
#pragma unroll
        for (int d = 0; d < 12; d++) {
            wI[d] = pack2(__ldg(pI + 2*d), __ldg(pI + 2*d + 1));
            wF[d] = pack2(__ldg(pF + 2*d), __ldg(pF + 2*d + 1));
            wG[d] = pack2(__ldg(pG + 2*d), __ldg(pG + 2*d + 1));
            wO[d] = pack2(__ldg(pO + 2*d), __ldg(pO + 2*d + 1));
        }
        wIt = __ldg(pI + 24); wFt = __ldg(pF + 24);
        wGt = __ldg(pG + 24); wOt = __ldg(pO + 24);
    } else {
#pragma unroll
        for (int d = 0; d < 12; d++) { wI[d] = 0ull; wF[d] = 0ull; wG[d] = 0ull; wO[d] = 0ull; }
    }

    float cst = active ? __ldg(c0row + dim) : 0.f;

    // init buffer 0 (padded layout) + mbarrier (count = 16 source CTAs)
    for (int i = tid; i < HN; i += TPB)
        sh_h[0][(i / 25) * 28 + (i % 25)] = h0row[i];
    if (tid == 0)
        asm volatile("mbarrier.init.shared.b64 [%0], %1;"
                     :: "r"(s2u((const void*)&sh_mbar)), "r"(CLU) : "memory");
    __syncthreads();

    // cluster-wide: buffers + mbarriers initialized everywhere
    asm volatile("barrier.cluster.arrive.aligned;" ::: "memory");
    asm volatile("barrier.cluster.wait.aligned;" ::: "memory");

    // precomputed remote addresses
    const uint32_t lbase = s2u(&sh_h[0][0]);
    uint32_t raddr0 = 0;
    if ((tid & 16) == 0) {   // even groups (all active); rank = lc, pair base = grp
        uint32_t la = lbase + (uint32_t)((cta * 28 + grp) * 4);
        asm("mapa.shared::cluster.u32 %0, %1, %2;" : "=r"(raddr0) : "r"(la), "r"(lc));
    }
    const uint32_t raddr1 = raddr0 + HPAD * 4;
    uint32_t mbar_raddr = 0;
    if (tid < CLU) {
        uint32_t la = s2u((const void*)&sh_mbar);
        asm("mapa.shared::cluster.u32 %0, %1, %2;" : "=r"(mbar_raddr) : "r"(la), "r"(tid));
    }
    const uint32_t mbar_local = s2u((const void*)&sh_mbar);

    // prefetch G gate for step 0 (lanes lc<4 load gate lc)
    float gval = 0.f;
    if (active && lc < 4) {
        size_t off = (size_t)(dir ? SEQN - 1 : 0) * GN + lc * 400 + dim;
        gval = __ldg(Ga + off);
        if (Gb) gval += __ldg(Gb + off);
    }

    for (int s = 0; s < SEQN; ++s) {
        const int buf = s & 1;
        const int t = dir ? (SEQN - 1 - s) : s;

        // ---- packed dot over this lane's 25-elem chunk ----
        unsigned long long aI = 0ull, aF = 0ull, aG = 0ull, aO = 0ull;
        const ulonglong2* hp = reinterpret_cast<const ulonglong2*>(&sh_h[buf][lc * 28]);
#pragma unroll
        for (int j = 0; j < 6; j++) {
            ulonglong2 v = hp[j];
            fma2(aI, wI[2*j],   v.x); fma2(aF, wF[2*j],   v.x);
            fma2(aG, wG[2*j],   v.x); fma2(aO, wO[2*j],   v.x);
            fma2(aI, wI[2*j+1], v.y); fma2(aF, wF[2*j+1], v.y);
            fma2(aG, wG[2*j+1], v.y); fma2(aO, wO[2*j+1], v.y);
        }
        float ai = hsum2(aI), af = hsum2(aF), ag = hsum2(aG), ao = hsum2(aO);
        {
            float v = sh_h[buf][lc * 28 + 24];
            ai = fmaf(wIt, v, ai); af = fmaf(wFt, v, af);
            ag = fmaf(wGt, v, ag); ao = fmaf(wOt, v, ao);
        }
#pragma unroll
        for (int m = 8; m >= 1; m >>= 1) {
            ai += __shfl_xor_sync(0xffffffffu, ai, m);
            af += __shfl_xor_sync(0xffffffffu, af, m);
            ag += __shfl_xor_sync(0xffffffffu, ag, m);
            ao += __shfl_xor_sync(0xffffffffu, ao, m);
        }

        float gi = __shfl_sync(0xffffffffu, gval, wbase + 0);
        float gf = __shfl_sync(0xffffffffu, gval, wbase + 1);
        float gg = __shfl_sync(0xffffffffu, gval, wbase + 2);
        float go = __shfl_sync(0xffffffffu, gval, wbase + 3);

        // activations computed by ALL lanes (dummy group produces finite junk)
        float I  = sig_apx(gi + ai);
        float F  = sig_apx(gf + af);
        float O  = sig_apx(go + ao);
        float Gv = tanh_apx(gg + ag);
        cst = fmaf(F, cst, I * Gv);
        float hN = O * tanh_apx(cst);

        // pair-pack: lanes 0-15 of each warp get partner dim's value
        float hNp = __shfl_xor_sync(0xffffffffu, hN, 16);
        if (active && lc == 0) sh_y[t][grp] = hN;     // SMEM staging, no STG
        if ((tid & 16) == 0) {                        // even grp: store pair to rank lc
            uint32_t ra = buf ? raddr0 : raddr1;
            asm volatile("st.shared::cluster.v2.f32 [%0], {%1, %2};"
                         :: "r"(ra), "f"(hN), "f"(hNp) : "memory");
        }

        if (s + 1 < SEQN) {
            // prefetch next step's G gates (loads don't delay the release)
            if (active && lc < 4) {
                const int tn = dir ? (SEQN - 2 - s) : (s + 1);
                size_t off = (size_t)tn * GN + lc * 400 + dim;
                gval = __ldg(Ga + off);
                if (Gb) gval += __ldg(Gb + off);
            }
            __syncthreads();   // all data stores issued before the release-arrive
            if (tid < CLU)
                asm volatile("mbarrier.arrive.release.cluster.shared::cluster.b64 _, [%0];"
                             :: "r"(mbar_raddr) : "memory");
            {
                uint32_t par = (uint32_t)(s & 1);
                asm volatile(
                    "{\n\t.reg .pred P;\n\t"
                    "LSTMW_%=:\n\t"
                    "mbarrier.try_wait.parity.acquire.cluster.shared::cta.b64 P, [%0], %1, 0x989680;\n\t"
                    "@P bra.uni LSTMD_%=;\n\t"
                    "bra.uni LSTMW_%=;\n\t"
                    "LSTMD_%=:\n\t}"
                    :: "r"(mbar_local), "r"(par) : "memory");
            }
        }
    }

    // bulk Y dump (once)
    __syncthreads();
    for (int idx = tid; idx < SEQN * DPC; idx += TPB) {
        int t = idx / DPC, d = idx % DPC;
        Y[(size_t)t * 800 + dir * HN + cta * DPC + d] = sh_y[t][d];
    }
}

// ---------------- output border (row 0 / col 0, corner) ----------------
__global__ void k_border(float* __restrict__ out) {
    int i = threadIdx.x;
    if (i < NP1) {
        out[i] = (i == 0) ? 1.f : 0.f;
        if (i > 0) out[(size_t)i * NP1] = 0.f;
    }
}

// ---------------- pairwise scorer (sums the two K-half partials) -----------
__global__ void __launch_bounds__(256)
k_scores(const float* __restrict__ b1v, const float* __restrict__ w2,
         const float* __restrict__ b2, float* __restrict__ out) {
    __shared__ float As[32][65];
    __shared__ float Bs[32][65];
    __shared__ float w2s[64];
    int tid = threadIdx.x;
    int tx = tid & 15, ty = tid >> 4;
    int i0 = blockIdx.y * 32, j0 = blockIdx.x * 32;

    float acc[2][2] = {};

    for (int k0 = 0; k0 < GN; k0 += 64) {
        int c = tid & 63;
        int rbase = tid >> 6;
        float bb = __ldg(b1v + k0 + c);
#pragma unroll
        for (int p = 0; p < 8; p++) {
            int rr = rbase + p * 4;
            size_t ia = (size_t)(i0 + rr) * GN + k0 + c;
            size_t ib = (size_t)(j0 + rr) * GN + k0 + c;
            As[rr][c] = g_A[0][ia] + g_A[1][ia] + bb;
            Bs[rr][c] = g_B[0][ib] + g_B[1][ib];
        }
        if (tid < 64) w2s[tid] = w2[k0 + tid];
        __syncthreads();
#pragma unroll 8
        for (int kk = 0; kk < 64; kk++) {
            float w  = w2s[kk];
            float a0 = As[2 * ty][kk],  a1  = As[2 * ty + 1][kk];
            float b0 = Bs[2 * tx][kk],  b1_ = Bs[2 * tx + 1][kk];
            acc[0][0] = fmaf(fmaxf(a0 + b0, 0.f), w, acc[0][0]);
            acc[0][1] = fmaf(fmaxf(a0 + b1_, 0.f), w, acc[0][1]);
            acc[1][0] = fmaf(fmaxf(a1 + b0, 0.f), w, acc[1][0]);
            acc[1][1] = fmaf(fmaxf(a1 + b1_, 0.f), w, acc[1][1]);
        }
        __syncthreads();
    }
    float bb2 = __ldg(b2);
#pragma unroll
    for (int ii = 0; ii < 2; ii++)
#pragma unroll
        for (int jj = 0; jj < 2; jj++) {
            int i = i0 + 2 * ty + ii, j = j0 + 2 * tx + jj;
            float v = acc[ii][jj] + bb2;
            if (i == j) v = 0.f;
            out[(size_t)(i + 1) * NP1 + (j + 1)] = v;
        }
}

// ---------------- launch ----------------
extern "C" void kernel_launch(void* const* d_in, const int* in_sizes, int n_in,
                              void* d_out, int out_size) {
    const int*   words    = (const int*)  d_in[0];
    const int*   tags     = (const int*)  d_in[1];
    // d_in[2] = arcs (unused by reference)
    const float* wemb     = (const float*)d_in[3];
    const float* temb     = (const float*)d_in[4];
    const float* h0       = (const float*)d_in[5];
    const float* c0       = (const float*)d_in[6];
    const float* w_ih_l0  = (const float*)d_in[7];
    const float* w_hh_l0  = (const float*)d_in[8];
    const float* b_ih_l0  = (const float*)d_in[9];
    const float* b_hh_l0  = (const float*)d_in[10];
    const float* w_ih_l0r = (const float*)d_in[11];
    const float* w_hh_l0r = (const float*)d_in[12];
    const float* b_ih_l0r = (const float*)d_in[13];
    const float* b_hh_l0r = (const float*)d_in[14];
    const float* w_ih_l1  = (const float*)d_in[15];
    const float* w_hh_l1  = (const float*)d_in[16];
    const float* b_ih_l1  = (const float*)d_in[17];
    const float* b_hh_l1  = (const float*)d_in[18];
    const float* w_ih_l1r = (const float*)d_in[19];
    const float* w_hh_l1r = (const float*)d_in[20];
    const float* b_ih_l1r = (const float*)d_in[21];
    const float* b_hh_l1r = (const float*)d_in[22];
    const float* mlp_w1   = (const float*)d_in[23];
    const float* mlp_b1   = (const float*)d_in[24];
    const float* mlp_w2   = (const float*)d_in[25];
    const float* mlp_b2   = (const float*)d_in[26];
    float* out = (float*)d_out;

    float *px, *pG0, *pG1, *py0, *phv, *pA, *pB;
    cudaGetSymbolAddress((void**)&px,  g_x);
    cudaGetSymbolAddress((void**)&pG0, g_G0);
    cudaGetSymbolAddress((void**)&pG1, g_G1);
    cudaGetSymbolAddress((void**)&py0, g_y0);
    cudaGetSymbolAddress((void**)&phv, g_hv);
    cudaGetSymbolAddress((void**)&pA,  g_A);
    cudaGetSymbolAddress((void**)&pB,  g_B);
    const size_t SG = (size_t)SEQN * GN;
    float* pG0f  = pG0;
    float* pG0b  = pG0 + SG;
    float* pG1f0 = pG1;            // [dir=0][half=0]
    float* pG1f1 = pG1 + SG;       // [dir=0][half=1]
    float* pG1b0 = pG1 + 2 * SG;   // [dir=1][half=0]
    float* pG1b1 = pG1 + 3 * SG;   // [dir=1][half=1]
    float* pA0 = pA,      *pA1 = pA + SG;
    float* pB0 = pB,      *pB1 = pB + SG;

    static int attr_done = 0;
    if (!attr_done) {
        cudaFuncSetAttribute(k_lstm, cudaFuncAttributeNonPortableClusterSizeAllowed, 1);
        attr_done = 1;
    }
    cudaLaunchConfig_t cfg = {};
    cfg.gridDim  = dim3(2 * CLU, 1, 1);
    cfg.blockDim = dim3(TPB, 1, 1);
    cfg.dynamicSmemBytes = 0;
    cfg.stream = 0;
    cudaLaunchAttribute lat[1];
    lat[0].id = cudaLaunchAttributeClusterDimension;
    lat[0].val.clusterDim.x = CLU;
    lat[0].val.clusterDim.y = 1;
    lat[0].val.clusterDim.z = 1;
    cfg.attrs = lat;
    cfg.numAttrs = 1;

    k_embed<<<(SEQN * HN + 255) / 256, 256>>>(words, tags, wemb, temb);

    // layer0 projections: K=400 unsplit, 2 problems
    k_gemm2<<<dim3(5, 25, 2), 256>>>(px, HN, w_ih_l0, w_ih_l0r, HN, 0, 0,
                                     b_ih_l0, b_ih_l0r, b_hh_l0, b_hh_l0r,
                                     pG0f, pG0f, pG0b, pG0b, 400);

    cudaLaunchKernelEx(&cfg, k_lstm, w_hh_l0, w_hh_l0r, h0, c0, 0);

    // layer1 projections: K=800 split into 2x400, 2 problems -> 500 blocks
    k_gemm2<<<dim3(5, 25, 4), 256>>>(py0, 800, w_ih_l1, w_ih_l1r, 800, 0, 0,
                                     b_ih_l1, b_ih_l1r, b_hh_l1, b_hh_l1r,
                                     pG1f0, pG1f1, pG1b0, pG1b1, 400);

    cudaLaunchKernelEx(&cfg, k_lstm, w_hh_l1, w_hh_l1r, h0, c0, 1);

    // MLP projections: K=800 split into 2x400 (partials summed in k_scores)
    k_gemm2<<<dim3(5, 25, 4), 256>>>(phv, 800, mlp_w1, mlp_w1, GN, 0, 800,
                                     nullptr, nullptr, nullptr, nullptr,
                                     pA0, pA1, pB0, pB1, 400);

    k_border<<<1, 352>>>(out);
    k_scores<<<dim3(10, 10), 256>>>(mlp_b1, mlp_w2, mlp_b2, out);
}